// round 7
// baseline (speedup 1.0000x reference)
#include <cuda_runtime.h>
#include <cstdint>

typedef unsigned long long ull;

#define BATCH 8192
#define SEQT  256
#define HID   32
#define RPW   3                              // batch rows per warp
#define ENC_CTAS ((BATCH + RPW - 1) / RPW)   // 2731

// scratch: decoder per-row gate preactivations, transposed for coalesced loads
__device__ float g_pre[4][BATCH];

// ---- f32x2 helpers (Blackwell packed fp32) ----
__device__ __forceinline__ void fma2(ull &acc, ull a, ull b) {
    asm("fma.rn.f32x2 %0, %1, %2, %0;" : "+l"(acc) : "l"(a), "l"(b));
}
__device__ __forceinline__ ull pack2(float a, float b) {
    ull r;
    asm("mov.b64 %0, {%1, %2};" : "=l"(r)
        : "r"(__float_as_uint(a)), "r"(__float_as_uint(b)));
    return r;
}
__device__ __forceinline__ float hsum2(ull v) {
    unsigned lo, hi;
    asm("mov.b64 {%0, %1}, %2;" : "=r"(lo), "=r"(hi) : "l"(v));
    return __uint_as_float(lo) + __uint_as_float(hi);
}

// ---- fast activations (EX2/RCP; ~2 ulp, saturate correctly) ----
__device__ __forceinline__ float sigm(float x) {
    return __fdividef(1.0f, 1.0f + __expf(-x));
}
__device__ __forceinline__ float tanhx(float x) {
    return 1.0f - __fdividef(2.0f, __expf(2.0f * x) + 1.0f);
}

// ============================================================================
// Encoder: ONE WARP per CTA, THREE batch rows per warp. 128 weight regs are
// shared across rows; each row is an independent recurrence chain (ILP).
// Lane j owns hidden unit j; gate rows i=j, f=32+j, g=64+j, o=96+j.
// h broadcast via smem ping-pong, read as 16B vectors (LDS.128).
// No cross-warp sync on the critical path.
// ============================================================================
__global__ void __launch_bounds__(32, 10) enc_kernel(
    const float* __restrict__ x,      // [B, T]
    const float* __restrict__ eWih,   // [128]
    const float* __restrict__ eWhh,   // [128, 32]
    const float* __restrict__ eBih,   // [128]
    const float* __restrict__ eBhh,   // [128]
    const float* __restrict__ dWih,   // [4, 32]
    const float* __restrict__ dBih,   // [4]
    const float* __restrict__ dBhh)   // [4]
{
    __shared__ float xs[RPW][SEQT];
    __shared__ __align__(16) ull hb[2][RPW][HID / 2];  // [parity][row][kpair]

    const int lane  = threadIdx.x;
    const int rbase = blockIdx.x * RPW;

    int rows[RPW];
    #pragma unroll
    for (int r = 0; r < RPW; ++r)
        rows[r] = min(rbase + r, BATCH - 1);   // clamp: last CTA duplicates row 8191

    // stage x rows (float4-coalesced)
    #pragma unroll
    for (int r = 0; r < RPW; ++r) {
        const float4* s4 = (const float4*)(x + (size_t)rows[r] * SEQT);
        ((float4*)xs[r])[lane]      = s4[lane];
        ((float4*)xs[r])[32 + lane] = s4[32 + lane];
    }

    // per-lane recurrent weights, packed over k-pairs (shared by all rows)
    ull wi[16], wf[16], wg[16], wo[16];
    {
        const ull* ri = (const ull*)(eWhh + (size_t)(      lane) * HID);
        const ull* rf = (const ull*)(eWhh + (size_t)(32  + lane) * HID);
        const ull* rg = (const ull*)(eWhh + (size_t)(64  + lane) * HID);
        const ull* ro = (const ull*)(eWhh + (size_t)(96  + lane) * HID);
        #pragma unroll
        for (int k = 0; k < 16; ++k) {
            wi[k] = ri[k]; wf[k] = rf[k]; wg[k] = rg[k]; wo[k] = ro[k];
        }
    }
    const float bi = eBih[lane]      + eBhh[lane];
    const float bf = eBih[32 + lane] + eBhh[32 + lane];
    const float bg = eBih[64 + lane] + eBhh[64 + lane];
    const float bo = eBih[96 + lane] + eBhh[96 + lane];
    const float vi = eWih[lane];
    const float vf = eWih[32 + lane];
    const float vg = eWih[64 + lane];
    const float vo = eWih[96 + lane];

    #pragma unroll
    for (int r = 0; r < RPW; ++r)
        ((float*)hb[0][r])[lane] = 0.0f;
    __syncwarp();

    float h[RPW], c[RPW];
    #pragma unroll
    for (int r = 0; r < RPW; ++r) { h[r] = 0.0f; c[r] = 0.0f; }

    #pragma unroll 1
    for (int t = 0; t < SEQT; t += 2) {
        #pragma unroll
        for (int p = 0; p < 2; ++p) {
            ull ai[RPW], af[RPW], ag[RPW], ao[RPW];
            #pragma unroll
            for (int r = 0; r < RPW; ++r) {
                const float xv = xs[r][t + p];
                ai[r] = pack2(fmaf(xv, vi, bi), 0.0f);
                af[r] = pack2(fmaf(xv, vf, bf), 0.0f);
                ag[r] = pack2(fmaf(xv, vg, bg), 0.0f);
                ao[r] = pack2(fmaf(xv, vo, bo), 0.0f);
            }

            #pragma unroll
            for (int k = 0; k < 8; ++k) {
                #pragma unroll
                for (int r = 0; r < RPW; ++r) {
                    const ulonglong2 h2 =
                        ((const ulonglong2*)hb[p][r])[k];   // LDS.128 broadcast
                    fma2(ai[r], wi[2 * k],     h2.x);
                    fma2(af[r], wf[2 * k],     h2.x);
                    fma2(ag[r], wg[2 * k],     h2.x);
                    fma2(ao[r], wo[2 * k],     h2.x);
                    fma2(ai[r], wi[2 * k + 1], h2.y);
                    fma2(af[r], wf[2 * k + 1], h2.y);
                    fma2(ag[r], wg[2 * k + 1], h2.y);
                    fma2(ao[r], wo[2 * k + 1], h2.y);
                }
            }

            #pragma unroll
            for (int r = 0; r < RPW; ++r) {
                const float I = sigm(hsum2(ai[r]));
                const float F = sigm(hsum2(af[r]));
                const float G = tanhx(hsum2(ag[r]));
                const float O = sigm(hsum2(ao[r]));
                c[r] = fmaf(F, c[r], I * G);
                h[r] = O * tanhx(c[r]);
                ((float*)hb[p ^ 1][r])[lane] = h[r];
            }
            __syncwarp();
        }
    }

    // decoder input projection per row: pg = sum_j dWih[g][j]*h[j]
    const float dw0 = dWih[lane];
    const float dw1 = dWih[32 + lane];
    const float dw2 = dWih[64 + lane];
    const float dw3 = dWih[96 + lane];
    #pragma unroll
    for (int r = 0; r < RPW; ++r) {
        float p0 = h[r] * dw0;
        float p1 = h[r] * dw1;
        float p2 = h[r] * dw2;
        float p3 = h[r] * dw3;
        #pragma unroll
        for (int m = 16; m > 0; m >>= 1) {
            p0 += __shfl_xor_sync(0xffffffffu, p0, m);
            p1 += __shfl_xor_sync(0xffffffffu, p1, m);
            p2 += __shfl_xor_sync(0xffffffffu, p2, m);
            p3 += __shfl_xor_sync(0xffffffffu, p3, m);
        }
        if (lane == 0) {
            g_pre[0][rows[r]] = p0 + dBih[0] + dBhh[0];
            g_pre[1][rows[r]] = p1 + dBih[1] + dBhh[1];
            g_pre[2][rows[r]] = p2 + dBih[2] + dBhh[2];
            g_pre[3][rows[r]] = p3 + dBih[3] + dBhh[3];
        }
    }
}

// ============================================================================
// Decoder: one batch row per THREAD (H=1 scalar recurrence). 8192 threads.
// ============================================================================
__global__ void __launch_bounds__(32) dec_kernel(
    const float* __restrict__ dWhh,   // [4]
    float* __restrict__ out)          // [B, T]
{
    const int r = blockIdx.x * 32 + threadIdx.x;

    const float pre0 = g_pre[0][r];
    const float pre1 = g_pre[1][r];
    const float pre2 = g_pre[2][r];
    const float pre3 = g_pre[3][r];
    const float q0 = dWhh[0], q1 = dWhh[1], q2 = dWhh[2], q3 = dWhh[3];

    float hd = 0.0f, cd = 0.0f;
    float* orow = out + (size_t)r * SEQT;

    #pragma unroll 1
    for (int t = 0; t < SEQT; t += 4) {
        float v[4];
        #pragma unroll
        for (int s = 0; s < 4; ++s) {
            const float I = sigm(fmaf(hd, q0, pre0));
            const float F = sigm(fmaf(hd, q1, pre1));
            const float G = tanhx(fmaf(hd, q2, pre2));
            const float O = sigm(fmaf(hd, q3, pre3));
            cd = fmaf(F, cd, I * G);
            hd = O * tanhx(cd);
            v[s] = hd;
        }
        *(float4*)(orow + t) = make_float4(v[0], v[1], v[2], v[3]);
    }
}

extern "C" void kernel_launch(void* const* d_in, const int* in_sizes, int n_in,
                              void* d_out, int out_size) {
    (void)in_sizes; (void)n_in; (void)out_size;
    enc_kernel<<<ENC_CTAS, 32>>>(
        (const float*)d_in[0],
        (const float*)d_in[1], (const float*)d_in[2],
        (const float*)d_in[3], (const float*)d_in[4],
        (const float*)d_in[5],
        (const float*)d_in[7], (const float*)d_in[8]);
    dec_kernel<<<BATCH / 32, 32>>>(
        (const float*)d_in[6],
        (float*)d_out);
}

// round 8
// speedup vs baseline: 1.0096x; 1.0096x over previous
#include <cuda_runtime.h>
#include <cstdint>

typedef unsigned long long ull;

#define BATCH 8192
#define SEQT  256
#define HID   32

// scratch: decoder per-row gate preactivations, transposed for coalesced loads
__device__ float g_pre[4][BATCH];

// ---- f32x2 helpers (Blackwell packed fp32) ----
__device__ __forceinline__ void fma2(ull &acc, ull a, ull b) {
    asm("fma.rn.f32x2 %0, %1, %2, %0;" : "+l"(acc) : "l"(a), "l"(b));
}
__device__ __forceinline__ ull pack2(float a, float b) {
    ull r;
    asm("mov.b64 %0, {%1, %2};" : "=l"(r)
        : "r"(__float_as_uint(a)), "r"(__float_as_uint(b)));
    return r;
}
__device__ __forceinline__ float hsum2(ull v) {
    unsigned lo, hi;
    asm("mov.b64 {%0, %1}, %2;" : "=r"(lo), "=r"(hi) : "l"(v));
    return __uint_as_float(lo) + __uint_as_float(hi);
}

// ---- fast activations (EX2/RCP; ~2 ulp, saturate correctly) ----
__device__ __forceinline__ float sigm(float x) {
    return __fdividef(1.0f, 1.0f + __expf(-x));
}
__device__ __forceinline__ float tanhx(float x) {
    return 1.0f - __fdividef(2.0f, __expf(2.0f * x) + 1.0f);
}

// GEMV phase: init accumulators with x-projection + bias, then 32-MAC GEMV
// against the h broadcast buffer (LDS.128).
#define GEMV(ai, af, ag, ao, buf, xv)                                   \
    do {                                                                \
        const float _xv = (xv);                                         \
        ai = pack2(fmaf(_xv, vi, bi), 0.0f);                            \
        af = pack2(fmaf(_xv, vf, bf), 0.0f);                            \
        ag = pack2(fmaf(_xv, vg, bg), 0.0f);                            \
        ao = pack2(fmaf(_xv, vo, bo), 0.0f);                            \
        _Pragma("unroll")                                               \
        for (int _k = 0; _k < 8; ++_k) {                                \
            const ulonglong2 _h2 = ((const ulonglong2*)(buf))[_k];      \
            fma2(ai, wi[2 * _k],     _h2.x);                            \
            fma2(af, wf[2 * _k],     _h2.x);                            \
            fma2(ag, wg[2 * _k],     _h2.x);                            \
            fma2(ao, wo[2 * _k],     _h2.x);                            \
            fma2(ai, wi[2 * _k + 1], _h2.y);                            \
            fma2(af, wf[2 * _k + 1], _h2.y);                            \
            fma2(ag, wg[2 * _k + 1], _h2.y);                            \
            fma2(ao, wo[2 * _k + 1], _h2.y);                            \
        }                                                               \
    } while (0)

// TAIL phase: activations + (c,h) update + publish h to the broadcast buffer.
#define TAIL(ai, af, ag, ao, cv, hv, buf)                               \
    do {                                                                \
        const float _I = sigm(hsum2(ai));                               \
        const float _F = sigm(hsum2(af));                               \
        const float _G = tanhx(hsum2(ag));                              \
        const float _O = sigm(hsum2(ao));                               \
        cv = fmaf(_F, cv, _I * _G);                                     \
        hv = _O * tanhx(cv);                                            \
        ((float*)(buf))[lane] = hv;                                     \
    } while (0)

// ============================================================================
// Encoder: ONE WARP per CTA, TWO batch rows per warp, SOFTWARE-PIPELINED:
// rows are skewed half a step so each row's MUFU/serial tail overlaps the
// other row's 64 independent fma2 (GEMV). Single h buffer per row (the skew
// plus one __syncwarp per half-step makes ping-pong unnecessary).
// ============================================================================
__global__ void __launch_bounds__(32, 10) enc_kernel(
    const float* __restrict__ x,      // [B, T]
    const float* __restrict__ eWih,   // [128]
    const float* __restrict__ eWhh,   // [128, 32]
    const float* __restrict__ eBih,   // [128]
    const float* __restrict__ eBhh,   // [128]
    const float* __restrict__ dWih,   // [4, 32]
    const float* __restrict__ dBih,   // [4]
    const float* __restrict__ dBhh)   // [4]
{
    __shared__ float xsA[SEQT], xsB[SEQT];
    __shared__ __align__(16) ull bufA[HID / 2], bufB[HID / 2];

    const int lane = threadIdx.x;
    const int rA   = blockIdx.x * 2;
    const int rB   = rA + 1;

    // stage both x rows (float4-coalesced)
    {
        const float4* a4 = (const float4*)(x + (size_t)rA * SEQT);
        const float4* b4 = (const float4*)(x + (size_t)rB * SEQT);
        ((float4*)xsA)[lane]      = a4[lane];
        ((float4*)xsA)[32 + lane] = a4[32 + lane];
        ((float4*)xsB)[lane]      = b4[lane];
        ((float4*)xsB)[32 + lane] = b4[32 + lane];
    }

    // per-lane recurrent weights, packed over k-pairs (shared by both rows)
    ull wi[16], wf[16], wg[16], wo[16];
    {
        const ull* ri = (const ull*)(eWhh + (size_t)(      lane) * HID);
        const ull* rf = (const ull*)(eWhh + (size_t)(32  + lane) * HID);
        const ull* rg = (const ull*)(eWhh + (size_t)(64  + lane) * HID);
        const ull* ro = (const ull*)(eWhh + (size_t)(96  + lane) * HID);
        #pragma unroll
        for (int k = 0; k < 16; ++k) {
            wi[k] = ri[k]; wf[k] = rf[k]; wg[k] = rg[k]; wo[k] = ro[k];
        }
    }
    const float bi = eBih[lane]      + eBhh[lane];
    const float bf = eBih[32 + lane] + eBhh[32 + lane];
    const float bg = eBih[64 + lane] + eBhh[64 + lane];
    const float bo = eBih[96 + lane] + eBhh[96 + lane];
    const float vi = eWih[lane];
    const float vf = eWih[32 + lane];
    const float vg = eWih[64 + lane];
    const float vo = eWih[96 + lane];

    ((float*)bufA)[lane] = 0.0f;
    ((float*)bufB)[lane] = 0.0f;
    __syncwarp();

    float hA = 0.0f, cA = 0.0f;
    float hB = 0.0f, cB = 0.0f;
    ull aiA, afA, agA, aoA, aiB, afB, agB, aoB;

    // pipeline prologue
    GEMV(aiA, afA, agA, aoA, bufA, xsA[0]);

    #pragma unroll 1
    for (int t = 0; t < SEQT - 1; ++t) {
        // tail(A,t) || GEMV(B,t)  — independent, interleaved by scheduler
        TAIL(aiA, afA, agA, aoA, cA, hA, bufA);
        GEMV(aiB, afB, agB, aoB, bufB, xsB[t]);
        __syncwarp();
        // tail(B,t) || GEMV(A,t+1)
        TAIL(aiB, afB, agB, aoB, cB, hB, bufB);
        GEMV(aiA, afA, agA, aoA, bufA, xsA[t + 1]);
        __syncwarp();
    }
    // pipeline epilogue: t = SEQT-1
    TAIL(aiA, afA, agA, aoA, cA, hA, bufA);
    GEMV(aiB, afB, agB, aoB, bufB, xsB[SEQT - 1]);
    __syncwarp();
    TAIL(aiB, afB, agB, aoB, cB, hB, bufB);

    // decoder input projection for both rows: pg = sum_j dWih[g][j]*h[j]
    float pA0 = hA * dWih[lane];
    float pA1 = hA * dWih[32 + lane];
    float pA2 = hA * dWih[64 + lane];
    float pA3 = hA * dWih[96 + lane];
    float pB0 = hB * dWih[lane];
    float pB1 = hB * dWih[32 + lane];
    float pB2 = hB * dWih[64 + lane];
    float pB3 = hB * dWih[96 + lane];
    #pragma unroll
    for (int m = 16; m > 0; m >>= 1) {
        pA0 += __shfl_xor_sync(0xffffffffu, pA0, m);
        pA1 += __shfl_xor_sync(0xffffffffu, pA1, m);
        pA2 += __shfl_xor_sync(0xffffffffu, pA2, m);
        pA3 += __shfl_xor_sync(0xffffffffu, pA3, m);
        pB0 += __shfl_xor_sync(0xffffffffu, pB0, m);
        pB1 += __shfl_xor_sync(0xffffffffu, pB1, m);
        pB2 += __shfl_xor_sync(0xffffffffu, pB2, m);
        pB3 += __shfl_xor_sync(0xffffffffu, pB3, m);
    }
    if (lane == 0) {
        g_pre[0][rA] = pA0 + dBih[0] + dBhh[0];
        g_pre[1][rA] = pA1 + dBih[1] + dBhh[1];
        g_pre[2][rA] = pA2 + dBih[2] + dBhh[2];
        g_pre[3][rA] = pA3 + dBih[3] + dBhh[3];
        g_pre[0][rB] = pB0 + dBih[0] + dBhh[0];
        g_pre[1][rB] = pB1 + dBih[1] + dBhh[1];
        g_pre[2][rB] = pB2 + dBih[2] + dBhh[2];
        g_pre[3][rB] = pB3 + dBih[3] + dBhh[3];
    }
}

// ============================================================================
// Decoder: one batch row per THREAD (H=1 scalar recurrence). 8192 threads.
// ============================================================================
__global__ void __launch_bounds__(32) dec_kernel(
    const float* __restrict__ dWhh,   // [4]
    float* __restrict__ out)          // [B, T]
{
    const int r = blockIdx.x * 32 + threadIdx.x;

    const float pre0 = g_pre[0][r];
    const float pre1 = g_pre[1][r];
    const float pre2 = g_pre[2][r];
    const float pre3 = g_pre[3][r];
    const float q0 = dWhh[0], q1 = dWhh[1], q2 = dWhh[2], q3 = dWhh[3];

    float hd = 0.0f, cd = 0.0f;
    float* orow = out + (size_t)r * SEQT;

    #pragma unroll 1
    for (int t = 0; t < SEQT; t += 4) {
        float v[4];
        #pragma unroll
        for (int s = 0; s < 4; ++s) {
            const float I = sigm(fmaf(hd, q0, pre0));
            const float F = sigm(fmaf(hd, q1, pre1));
            const float G = tanhx(fmaf(hd, q2, pre2));
            const float O = sigm(fmaf(hd, q3, pre3));
            cd = fmaf(F, cd, I * G);
            hd = O * tanhx(cd);
            v[s] = hd;
        }
        *(float4*)(orow + t) = make_float4(v[0], v[1], v[2], v[3]);
    }
}

extern "C" void kernel_launch(void* const* d_in, const int* in_sizes, int n_in,
                              void* d_out, int out_size) {
    (void)in_sizes; (void)n_in; (void)out_size;
    enc_kernel<<<BATCH / 2, 32>>>(
        (const float*)d_in[0],
        (const float*)d_in[1], (const float*)d_in[2],
        (const float*)d_in[3], (const float*)d_in[4],
        (const float*)d_in[5],
        (const float*)d_in[7], (const float*)d_in[8]);
    dec_kernel<<<BATCH / 32, 32>>>(
        (const float*)d_in[6],
        (float*)d_out);
}

// round 9
// speedup vs baseline: 1.1328x; 1.1221x over previous
#include <cuda_runtime.h>
#include <cstdint>

typedef unsigned long long ull;

#define BATCH 8192
#define SEQT  256
#define HID   32

// scratch: decoder per-row gate preactivations, transposed for coalesced loads
__device__ float g_pre[4][BATCH];

// ---- f32x2 helpers (Blackwell packed fp32) ----
__device__ __forceinline__ void fma2(ull &acc, ull a, ull b) {
    asm("fma.rn.f32x2 %0, %1, %2, %0;" : "+l"(acc) : "l"(a), "l"(b));
}
__device__ __forceinline__ void mul2(ull &a, ull b) {
    asm("mul.rn.f32x2 %0, %0, %1;" : "+l"(a) : "l"(b));
}
__device__ __forceinline__ ull pack2(float a, float b) {
    ull r;
    asm("mov.b64 %0, {%1, %2};" : "=l"(r)
        : "r"(__float_as_uint(a)), "r"(__float_as_uint(b)));
    return r;
}
__device__ __forceinline__ float hsum2(ull v) {
    unsigned lo, hi;
    asm("mov.b64 {%0, %1}, %2;" : "=r"(lo), "=r"(hi) : "l"(v));
    return __uint_as_float(lo) + __uint_as_float(hi);
}

// ---- activations ----
// MUFU.TANH (approx) — used ONLY for sigmoid gates (errors damped through c).
__device__ __forceinline__ float tanha(float x) {
    float y;
    asm("tanh.approx.f32 %0, %1;" : "=f"(y) : "f"(x));
    return y;
}
// sigmoid with the 1/2 input scale pre-folded into weights: sig = 0.5*tanh(acc)+0.5
__device__ __forceinline__ float sigm_pre(float acc_half_x) {
    return fmaf(0.5f, tanha(acc_half_x), 0.5f);
}
// precise tanh (EX2/RCP, ~2 ulp) — for g-gate and tanh(c), which feed c/h directly
__device__ __forceinline__ float tanhx(float x) {
    return 1.0f - __fdividef(2.0f, __expf(2.0f * x) + 1.0f);
}

// ============================================================================
// Encoder: ONE WARP per CTA, TWO batch rows per warp (shared weight regs,
// two independent recurrence chains). Lane j owns hidden unit j; gate rows
// i=j, f=32+j, g=64+j, o=96+j. i/f/o weights+biases are pre-scaled by 0.5 so
// sigmoids become one MUFU.TANH + one FMA. h broadcast via smem ping-pong
// read as LDS.128. No cross-warp sync on the critical path.
// ============================================================================
__global__ void __launch_bounds__(32, 11) enc_kernel(
    const float* __restrict__ x,      // [B, T]
    const float* __restrict__ eWih,   // [128]
    const float* __restrict__ eWhh,   // [128, 32]
    const float* __restrict__ eBih,   // [128]
    const float* __restrict__ eBhh,   // [128]
    const float* __restrict__ dWih,   // [4, 32]
    const float* __restrict__ dBih,   // [4]
    const float* __restrict__ dBhh)   // [4]
{
    __shared__ float xsA[SEQT], xsB[SEQT];
    __shared__ __align__(16) ull hbA[2][HID / 2], hbB[2][HID / 2];

    const int lane = threadIdx.x;
    const int rA   = blockIdx.x * 2;
    const int rB   = rA + 1;

    // stage both x rows (float4-coalesced)
    {
        const float4* a4 = (const float4*)(x + (size_t)rA * SEQT);
        const float4* b4 = (const float4*)(x + (size_t)rB * SEQT);
        ((float4*)xsA)[lane]      = a4[lane];
        ((float4*)xsA)[32 + lane] = a4[32 + lane];
        ((float4*)xsB)[lane]      = b4[lane];
        ((float4*)xsB)[32 + lane] = b4[32 + lane];
    }

    // per-lane recurrent weights, packed over k-pairs (shared by both rows).
    // i/f/o rows scaled by 0.5 (sigmoid half-input fold); g row unscaled.
    ull wi[16], wf[16], wg[16], wo[16];
    {
        const ull half2 = pack2(0.5f, 0.5f);
        const ull* ri = (const ull*)(eWhh + (size_t)(      lane) * HID);
        const ull* rf = (const ull*)(eWhh + (size_t)(32  + lane) * HID);
        const ull* rg = (const ull*)(eWhh + (size_t)(64  + lane) * HID);
        const ull* ro = (const ull*)(eWhh + (size_t)(96  + lane) * HID);
        #pragma unroll
        for (int k = 0; k < 16; ++k) {
            wi[k] = ri[k]; mul2(wi[k], half2);
            wf[k] = rf[k]; mul2(wf[k], half2);
            wg[k] = rg[k];
            wo[k] = ro[k]; mul2(wo[k], half2);
        }
    }
    const float bi = 0.5f * (eBih[lane]      + eBhh[lane]);
    const float bf = 0.5f * (eBih[32 + lane] + eBhh[32 + lane]);
    const float bg =        (eBih[64 + lane] + eBhh[64 + lane]);
    const float bo = 0.5f * (eBih[96 + lane] + eBhh[96 + lane]);
    const float vi = 0.5f * eWih[lane];
    const float vf = 0.5f * eWih[32 + lane];
    const float vg =        eWih[64 + lane];
    const float vo = 0.5f * eWih[96 + lane];

    ((float*)hbA[0])[lane] = 0.0f;
    ((float*)hbB[0])[lane] = 0.0f;
    __syncwarp();

    float hA = 0.0f, cA = 0.0f;
    float hB = 0.0f, cB = 0.0f;

    #pragma unroll 1
    for (int t = 0; t < SEQT; t += 2) {
        #pragma unroll
        for (int p = 0; p < 2; ++p) {
            const ulonglong2* ra = (const ulonglong2*)hbA[p];
            const ulonglong2* rb = (const ulonglong2*)hbB[p];
            const float xa = xsA[t + p];
            const float xb = xsB[t + p];

            ull aiA = pack2(fmaf(xa, vi, bi), 0.0f);
            ull afA = pack2(fmaf(xa, vf, bf), 0.0f);
            ull agA = pack2(fmaf(xa, vg, bg), 0.0f);
            ull aoA = pack2(fmaf(xa, vo, bo), 0.0f);
            ull aiB = pack2(fmaf(xb, vi, bi), 0.0f);
            ull afB = pack2(fmaf(xb, vf, bf), 0.0f);
            ull agB = pack2(fmaf(xb, vg, bg), 0.0f);
            ull aoB = pack2(fmaf(xb, vo, bo), 0.0f);

            #pragma unroll
            for (int k = 0; k < 8; ++k) {
                const ulonglong2 ha = ra[k];     // LDS.128 broadcast
                const ulonglong2 hb = rb[k];
                fma2(aiA, wi[2 * k],     ha.x);
                fma2(aiB, wi[2 * k],     hb.x);
                fma2(afA, wf[2 * k],     ha.x);
                fma2(afB, wf[2 * k],     hb.x);
                fma2(agA, wg[2 * k],     ha.x);
                fma2(agB, wg[2 * k],     hb.x);
                fma2(aoA, wo[2 * k],     ha.x);
                fma2(aoB, wo[2 * k],     hb.x);
                fma2(aiA, wi[2 * k + 1], ha.y);
                fma2(aiB, wi[2 * k + 1], hb.y);
                fma2(afA, wf[2 * k + 1], ha.y);
                fma2(afB, wf[2 * k + 1], hb.y);
                fma2(agA, wg[2 * k + 1], ha.y);
                fma2(agB, wg[2 * k + 1], hb.y);
                fma2(aoA, wo[2 * k + 1], ha.y);
                fma2(aoB, wo[2 * k + 1], hb.y);
            }

            // two independent activation/update chains
            const float IA = sigm_pre(hsum2(aiA));
            const float IB = sigm_pre(hsum2(aiB));
            const float FA = sigm_pre(hsum2(afA));
            const float FB = sigm_pre(hsum2(afB));
            const float GA = tanhx(hsum2(agA));
            const float GB = tanhx(hsum2(agB));
            const float OA = sigm_pre(hsum2(aoA));
            const float OB = sigm_pre(hsum2(aoB));
            cA = fmaf(FA, cA, IA * GA);
            cB = fmaf(FB, cB, IB * GB);
            hA = OA * tanhx(cA);
            hB = OB * tanhx(cB);

            ((float*)hbA[p ^ 1])[lane] = hA;
            ((float*)hbB[p ^ 1])[lane] = hB;
            __syncwarp();
        }
    }

    // decoder input projection for both rows: pg = sum_j dWih[g][j]*h[j]
    float pA0 = hA * dWih[lane];
    float pA1 = hA * dWih[32 + lane];
    float pA2 = hA * dWih[64 + lane];
    float pA3 = hA * dWih[96 + lane];
    float pB0 = hB * dWih[lane];
    float pB1 = hB * dWih[32 + lane];
    float pB2 = hB * dWih[64 + lane];
    float pB3 = hB * dWih[96 + lane];
    #pragma unroll
    for (int m = 16; m > 0; m >>= 1) {
        pA0 += __shfl_xor_sync(0xffffffffu, pA0, m);
        pA1 += __shfl_xor_sync(0xffffffffu, pA1, m);
        pA2 += __shfl_xor_sync(0xffffffffu, pA2, m);
        pA3 += __shfl_xor_sync(0xffffffffu, pA3, m);
        pB0 += __shfl_xor_sync(0xffffffffu, pB0, m);
        pB1 += __shfl_xor_sync(0xffffffffu, pB1, m);
        pB2 += __shfl_xor_sync(0xffffffffu, pB2, m);
        pB3 += __shfl_xor_sync(0xffffffffu, pB3, m);
    }
    if (lane == 0) {
        g_pre[0][rA] = pA0 + dBih[0] + dBhh[0];
        g_pre[1][rA] = pA1 + dBih[1] + dBhh[1];
        g_pre[2][rA] = pA2 + dBih[2] + dBhh[2];
        g_pre[3][rA] = pA3 + dBih[3] + dBhh[3];
        g_pre[0][rB] = pB0 + dBih[0] + dBhh[0];
        g_pre[1][rB] = pB1 + dBih[1] + dBhh[1];
        g_pre[2][rB] = pB2 + dBih[2] + dBhh[2];
        g_pre[3][rB] = pB3 + dBih[3] + dBhh[3];
    }
}

// ============================================================================
// Decoder: one batch row per THREAD (H=1 scalar recurrence). 8192 threads.
// Same hedged activations: sigmoids via MUFU.TANH (inputs pre-halved),
// g-gate and tanh(c) precise.
// ============================================================================
__global__ void __launch_bounds__(32) dec_kernel(
    const float* __restrict__ dWhh,   // [4]
    float* __restrict__ out)          // [B, T]
{
    const int r = blockIdx.x * 32 + threadIdx.x;

    const float pre0 = 0.5f * g_pre[0][r];
    const float pre1 = 0.5f * g_pre[1][r];
    const float pre2 =        g_pre[2][r];
    const float pre3 = 0.5f * g_pre[3][r];
    const float q0 = 0.5f * dWhh[0];
    const float q1 = 0.5f * dWhh[1];
    const float q2 =        dWhh[2];
    const float q3 = 0.5f * dWhh[3];

    float hd = 0.0f, cd = 0.0f;
    float* orow = out + (size_t)r * SEQT;

    #pragma unroll 1
    for (int t = 0; t < SEQT; t += 4) {
        float v[4];
        #pragma unroll
        for (int s = 0; s < 4; ++s) {
            const float I = sigm_pre(fmaf(hd, q0, pre0));
            const float F = sigm_pre(fmaf(hd, q1, pre1));
            const float G = tanhx(fmaf(hd, q2, pre2));
            const float O = sigm_pre(fmaf(hd, q3, pre3));
            cd = fmaf(F, cd, I * G);
            hd = O * tanhx(cd);
            v[s] = hd;
        }
        *(float4*)(orow + t) = make_float4(v[0], v[1], v[2], v[3]);
    }
}

extern "C" void kernel_launch(void* const* d_in, const int* in_sizes, int n_in,
                              void* d_out, int out_size) {
    (void)in_sizes; (void)n_in; (void)out_size;
    enc_kernel<<<BATCH / 2, 32>>>(
        (const float*)d_in[0],
        (const float*)d_in[1], (const float*)d_in[2],
        (const float*)d_in[3], (const float*)d_in[4],
        (const float*)d_in[5],
        (const float*)d_in[7], (const float*)d_in[8]);
    dec_kernel<<<BATCH / 32, 32>>>(
        (const float*)d_in[6],
        (float*)d_out);
}

// round 10
// speedup vs baseline: 1.2964x; 1.1444x over previous
#include <cuda_runtime.h>
#include <cstdint>

typedef unsigned long long ull;

#define BATCH 8192
#define SEQT  256
#define HID   32

// scratch: decoder per-row gate preactivations, transposed for coalesced loads
__device__ float g_pre[4][BATCH];

// ---- f32x2 helpers (Blackwell packed fp32) ----
__device__ __forceinline__ void fma2(ull &acc, ull a, ull b) {
    asm("fma.rn.f32x2 %0, %1, %2, %0;" : "+l"(acc) : "l"(a), "l"(b));
}
__device__ __forceinline__ void mul2(ull &a, ull b) {
    asm("mul.rn.f32x2 %0, %0, %1;" : "+l"(a) : "l"(b));
}
__device__ __forceinline__ ull pack2(float a, float b) {
    ull r;
    asm("mov.b64 %0, {%1, %2};" : "=l"(r)
        : "r"(__float_as_uint(a)), "r"(__float_as_uint(b)));
    return r;
}
__device__ __forceinline__ float hsum2(ull v) {
    unsigned lo, hi;
    asm("mov.b64 {%0, %1}, %2;" : "=r"(lo), "=r"(hi) : "l"(v));
    return __uint_as_float(lo) + __uint_as_float(hi);
}

// ---- activations: all MUFU.TANH (measured error impact ~1e-5 scale,
//      strongly damped by the gated recurrence; threshold is 1e-3) ----
__device__ __forceinline__ float tanha(float x) {
    float y;
    asm("tanh.approx.f32 %0, %1;" : "=f"(y) : "f"(x));
    return y;
}
// sigmoid with the 1/2 input scale pre-folded into weights: sig = 0.5*tanh(acc)+0.5
__device__ __forceinline__ float sigm_pre(float acc_half_x) {
    return fmaf(0.5f, tanha(acc_half_x), 0.5f);
}

// ============================================================================
// Encoder: ONE WARP per CTA, TWO batch rows per warp (shared weight regs,
// two independent recurrence chains). Lane j owns hidden unit j; gate rows
// i=j, f=32+j, g=64+j, o=96+j. i/f/o weights+biases pre-scaled by 0.5 so
// sigmoids are one MUFU.TANH + one FMA; g-gate and tanh(c) also MUFU.TANH.
// h broadcast via smem ping-pong read as LDS.128. No cross-warp sync on the
// critical path.
// ============================================================================
__global__ void __launch_bounds__(32, 11) enc_kernel(
    const float* __restrict__ x,      // [B, T]
    const float* __restrict__ eWih,   // [128]
    const float* __restrict__ eWhh,   // [128, 32]
    const float* __restrict__ eBih,   // [128]
    const float* __restrict__ eBhh,   // [128]
    const float* __restrict__ dWih,   // [4, 32]
    const float* __restrict__ dBih,   // [4]
    const float* __restrict__ dBhh)   // [4]
{
    __shared__ float xsA[SEQT], xsB[SEQT];
    __shared__ __align__(16) ull hbA[2][HID / 2], hbB[2][HID / 2];

    const int lane = threadIdx.x;
    const int rA   = blockIdx.x * 2;
    const int rB   = rA + 1;

    // stage both x rows (float4-coalesced)
    {
        const float4* a4 = (const float4*)(x + (size_t)rA * SEQT);
        const float4* b4 = (const float4*)(x + (size_t)rB * SEQT);
        ((float4*)xsA)[lane]      = a4[lane];
        ((float4*)xsA)[32 + lane] = a4[32 + lane];
        ((float4*)xsB)[lane]      = b4[lane];
        ((float4*)xsB)[32 + lane] = b4[32 + lane];
    }

    // per-lane recurrent weights, packed over k-pairs (shared by both rows).
    // i/f/o rows scaled by 0.5 (sigmoid half-input fold); g row unscaled.
    ull wi[16], wf[16], wg[16], wo[16];
    {
        const ull half2 = pack2(0.5f, 0.5f);
        const ull* ri = (const ull*)(eWhh + (size_t)(      lane) * HID);
        const ull* rf = (const ull*)(eWhh + (size_t)(32  + lane) * HID);
        const ull* rg = (const ull*)(eWhh + (size_t)(64  + lane) * HID);
        const ull* ro = (const ull*)(eWhh + (size_t)(96  + lane) * HID);
        #pragma unroll
        for (int k = 0; k < 16; ++k) {
            wi[k] = ri[k]; mul2(wi[k], half2);
            wf[k] = rf[k]; mul2(wf[k], half2);
            wg[k] = rg[k];
            wo[k] = ro[k]; mul2(wo[k], half2);
        }
    }
    const float bi = 0.5f * (eBih[lane]      + eBhh[lane]);
    const float bf = 0.5f * (eBih[32 + lane] + eBhh[32 + lane]);
    const float bg =        (eBih[64 + lane] + eBhh[64 + lane]);
    const float bo = 0.5f * (eBih[96 + lane] + eBhh[96 + lane]);
    const float vi = 0.5f * eWih[lane];
    const float vf = 0.5f * eWih[32 + lane];
    const float vg =        eWih[64 + lane];
    const float vo = 0.5f * eWih[96 + lane];

    ((float*)hbA[0])[lane] = 0.0f;
    ((float*)hbB[0])[lane] = 0.0f;
    __syncwarp();

    float hA = 0.0f, cA = 0.0f;
    float hB = 0.0f, cB = 0.0f;

    #pragma unroll 1
    for (int t = 0; t < SEQT; t += 2) {
        #pragma unroll
        for (int p = 0; p < 2; ++p) {
            const ulonglong2* ra = (const ulonglong2*)hbA[p];
            const ulonglong2* rb = (const ulonglong2*)hbB[p];
            const float xa = xsA[t + p];
            const float xb = xsB[t + p];

            ull aiA = pack2(fmaf(xa, vi, bi), 0.0f);
            ull afA = pack2(fmaf(xa, vf, bf), 0.0f);
            ull agA = pack2(fmaf(xa, vg, bg), 0.0f);
            ull aoA = pack2(fmaf(xa, vo, bo), 0.0f);
            ull aiB = pack2(fmaf(xb, vi, bi), 0.0f);
            ull afB = pack2(fmaf(xb, vf, bf), 0.0f);
            ull agB = pack2(fmaf(xb, vg, bg), 0.0f);
            ull aoB = pack2(fmaf(xb, vo, bo), 0.0f);

            #pragma unroll
            for (int k = 0; k < 8; ++k) {
                const ulonglong2 ha = ra[k];     // LDS.128 broadcast
                const ulonglong2 hb = rb[k];
                fma2(aiA, wi[2 * k],     ha.x);
                fma2(aiB, wi[2 * k],     hb.x);
                fma2(afA, wf[2 * k],     ha.x);
                fma2(afB, wf[2 * k],     hb.x);
                fma2(agA, wg[2 * k],     ha.x);
                fma2(agB, wg[2 * k],     hb.x);
                fma2(aoA, wo[2 * k],     ha.x);
                fma2(aoB, wo[2 * k],     hb.x);
                fma2(aiA, wi[2 * k + 1], ha.y);
                fma2(aiB, wi[2 * k + 1], hb.y);
                fma2(afA, wf[2 * k + 1], ha.y);
                fma2(afB, wf[2 * k + 1], hb.y);
                fma2(agA, wg[2 * k + 1], ha.y);
                fma2(agB, wg[2 * k + 1], hb.y);
                fma2(aoA, wo[2 * k + 1], ha.y);
                fma2(aoB, wo[2 * k + 1], hb.y);
            }

            // two independent activation/update chains — all MUFU.TANH
            const float IA = sigm_pre(hsum2(aiA));
            const float IB = sigm_pre(hsum2(aiB));
            const float FA = sigm_pre(hsum2(afA));
            const float FB = sigm_pre(hsum2(afB));
            const float GA = tanha(hsum2(agA));
            const float GB = tanha(hsum2(agB));
            const float OA = sigm_pre(hsum2(aoA));
            const float OB = sigm_pre(hsum2(aoB));
            cA = fmaf(FA, cA, IA * GA);
            cB = fmaf(FB, cB, IB * GB);
            hA = OA * tanha(cA);
            hB = OB * tanha(cB);

            ((float*)hbA[p ^ 1])[lane] = hA;
            ((float*)hbB[p ^ 1])[lane] = hB;
            __syncwarp();
        }
    }

    // decoder input projection for both rows: pg = sum_j dWih[g][j]*h[j]
    float pA0 = hA * dWih[lane];
    float pA1 = hA * dWih[32 + lane];
    float pA2 = hA * dWih[64 + lane];
    float pA3 = hA * dWih[96 + lane];
    float pB0 = hB * dWih[lane];
    float pB1 = hB * dWih[32 + lane];
    float pB2 = hB * dWih[64 + lane];
    float pB3 = hB * dWih[96 + lane];
    #pragma unroll
    for (int m = 16; m > 0; m >>= 1) {
        pA0 += __shfl_xor_sync(0xffffffffu, pA0, m);
        pA1 += __shfl_xor_sync(0xffffffffu, pA1, m);
        pA2 += __shfl_xor_sync(0xffffffffu, pA2, m);
        pA3 += __shfl_xor_sync(0xffffffffu, pA3, m);
        pB0 += __shfl_xor_sync(0xffffffffu, pB0, m);
        pB1 += __shfl_xor_sync(0xffffffffu, pB1, m);
        pB2 += __shfl_xor_sync(0xffffffffu, pB2, m);
        pB3 += __shfl_xor_sync(0xffffffffu, pB3, m);
    }
    if (lane == 0) {
        g_pre[0][rA] = pA0 + dBih[0] + dBhh[0];
        g_pre[1][rA] = pA1 + dBih[1] + dBhh[1];
        g_pre[2][rA] = pA2 + dBih[2] + dBhh[2];
        g_pre[3][rA] = pA3 + dBih[3] + dBhh[3];
        g_pre[0][rB] = pB0 + dBih[0] + dBhh[0];
        g_pre[1][rB] = pB1 + dBih[1] + dBhh[1];
        g_pre[2][rB] = pB2 + dBih[2] + dBhh[2];
        g_pre[3][rB] = pB3 + dBih[3] + dBhh[3];
    }
}

// ============================================================================
// Decoder: one batch row per THREAD (H=1 scalar recurrence). 8192 threads.
// All activations via MUFU.TANH (sigmoid inputs pre-halved).
// ============================================================================
__global__ void __launch_bounds__(32) dec_kernel(
    const float* __restrict__ dWhh,   // [4]
    float* __restrict__ out)          // [B, T]
{
    const int r = blockIdx.x * 32 + threadIdx.x;

    const float pre0 = 0.5f * g_pre[0][r];
    const float pre1 = 0.5f * g_pre[1][r];
    const float pre2 =        g_pre[2][r];
    const float pre3 = 0.5f * g_pre[3][r];
    const float q0 = 0.5f * dWhh[0];
    const float q1 = 0.5f * dWhh[1];
    const float q2 =        dWhh[2];
    const float q3 = 0.5f * dWhh[3];

    float hd = 0.0f, cd = 0.0f;
    float* orow = out + (size_t)r * SEQT;

    #pragma unroll 1
    for (int t = 0; t < SEQT; t += 4) {
        float v[4];
        #pragma unroll
        for (int s = 0; s < 4; ++s) {
            const float I = sigm_pre(fmaf(hd, q0, pre0));
            const float F = sigm_pre(fmaf(hd, q1, pre1));
            const float G = tanha(fmaf(hd, q2, pre2));
            const float O = sigm_pre(fmaf(hd, q3, pre3));
            cd = fmaf(F, cd, I * G);
            hd = O * tanha(cd);
            v[s] = hd;
        }
        *(float4*)(orow + t) = make_float4(v[0], v[1], v[2], v[3]);
    }
}

extern "C" void kernel_launch(void* const* d_in, const int* in_sizes, int n_in,
                              void* d_out, int out_size) {
    (void)in_sizes; (void)n_in; (void)out_size;
    enc_kernel<<<BATCH / 2, 32>>>(
        (const float*)d_in[0],
        (const float*)d_in[1], (const float*)d_in[2],
        (const float*)d_in[3], (const float*)d_in[4],
        (const float*)d_in[5],
        (const float*)d_in[7], (const float*)d_in[8]);
    dec_kernel<<<BATCH / 32, 32>>>(
        (const float*)d_in[6],
        (float*)d_out);
}

// round 11
// speedup vs baseline: 1.3750x; 1.0606x over previous
#include <cuda_runtime.h>
#include <cstdint>

typedef unsigned long long ull;

#define BATCH 8192
#define SEQT  256
#define HID   32

// scratch: decoder per-row gate preactivations, transposed for coalesced loads
__device__ float g_pre[4][BATCH];

// ---- f32x2 helpers ----
__device__ __forceinline__ void fma2(ull &acc, ull a, ull b) {
    asm("fma.rn.f32x2 %0, %1, %2, %0;" : "+l"(acc) : "l"(a), "l"(b));
}
__device__ __forceinline__ ull pack2(float a, float b) {
    ull r;
    asm("mov.b64 %0, {%1, %2};" : "=l"(r)
        : "r"(__float_as_uint(a)), "r"(__float_as_uint(b)));
    return r;
}
__device__ __forceinline__ float hsum2(ull v) {
    unsigned lo, hi;
    asm("mov.b64 {%0, %1}, %2;" : "=r"(lo), "=r"(hi) : "l"(v));
    return __uint_as_float(lo) + __uint_as_float(hi);
}
__device__ __forceinline__ void unpackf2(ull v, float &a, float &b) {
    unsigned lo, hi;
    asm("mov.b64 {%0, %1}, %2;" : "=r"(lo), "=r"(hi) : "l"(v));
    a = __uint_as_float(lo); b = __uint_as_float(hi);
}

// ---- bf16x2 helpers ----
__device__ __forceinline__ void hfma2(unsigned &acc, unsigned a, unsigned b) {
    asm("fma.rn.bf16x2 %0, %1, %2, %0;" : "+r"(acc) : "r"(a), "r"(b));
}
// pack (hi, lo) floats into bf16x2
__device__ __forceinline__ unsigned bfpack(float hi, float lo) {
    unsigned r;
    asm("cvt.rn.bf16x2.f32 %0, %1, %2;" : "=r"(r) : "f"(hi), "f"(lo));
    return r;
}
// horizontal sum of a bf16x2 accumulator in f32 (bf16->f32 is an exact shift)
__device__ __forceinline__ float bfsum(unsigned v) {
    return __uint_as_float(v << 16) + __uint_as_float(v & 0xffff0000u);
}

// ---- activations: all MUFU.TANH (measured final error ~1e-5 scale) ----
__device__ __forceinline__ float tanha(float x) {
    float y;
    asm("tanh.approx.f32 %0, %1;" : "=f"(y) : "f"(x));
    return y;
}
__device__ __forceinline__ float sigm_pre(float acc_half_x) {   // sig(2x) of acc
    return fmaf(0.5f, tanha(acc_half_x), 0.5f);
}

// ============================================================================
// Encoder: ONE WARP per CTA, TWO rows per warp. Sigmoid-gate weights (i,f,o,
// pre-scaled by 0.5) stored as bf16x2 -> HFMA2 (errors measured-damped by the
// recurrence); g-gate kept exact f32x2. Weight regs 128 -> ~80 per lane =>
// 14 warps/SM and an integral 2-wave schedule. h broadcast via smem ping-pong
// in BOTH f32 (g GEMV) and bf16 (i/f/o GEMV).
// ============================================================================
__global__ void __launch_bounds__(32, 14) enc_kernel(
    const float* __restrict__ x,      // [B, T]
    const float* __restrict__ eWih,   // [128]
    const float* __restrict__ eWhh,   // [128, 32]
    const float* __restrict__ eBih,   // [128]
    const float* __restrict__ eBhh,   // [128]
    const float* __restrict__ dWih,   // [4, 32]
    const float* __restrict__ dBih,   // [4]
    const float* __restrict__ dBhh)   // [4]
{
    __shared__ float xsA[SEQT], xsB[SEQT];
    __shared__ __align__(16) ull            hfA[2][HID / 2], hfB[2][HID / 2]; // f32 pairs
    __shared__ __align__(16) unsigned short hbA[2][HID],     hbB[2][HID];     // bf16

    const int lane = threadIdx.x;
    const int rA   = blockIdx.x * 2;
    const int rB   = rA + 1;

    // stage both x rows (float4-coalesced)
    {
        const float4* a4 = (const float4*)(x + (size_t)rA * SEQT);
        const float4* b4 = (const float4*)(x + (size_t)rB * SEQT);
        ((float4*)xsA)[lane]      = a4[lane];
        ((float4*)xsA)[32 + lane] = a4[32 + lane];
        ((float4*)xsB)[lane]      = b4[lane];
        ((float4*)xsB)[32 + lane] = b4[32 + lane];
    }

    // ---- per-lane weights ----
    // i/f/o rows: 0.5-scaled, bf16x2 (16 regs each). g row: exact f32x2 pairs.
    unsigned wI[16], wF[16], wO[16];
    ull      wG[16];
    {
        const ull* ri = (const ull*)(eWhh + (size_t)(      lane) * HID);
        const ull* rf = (const ull*)(eWhh + (size_t)(32  + lane) * HID);
        const ull* rg = (const ull*)(eWhh + (size_t)(64  + lane) * HID);
        const ull* ro = (const ull*)(eWhh + (size_t)(96  + lane) * HID);
        #pragma unroll
        for (int k = 0; k < 16; ++k) {
            float lo, hi;
            unpackf2(ri[k], lo, hi);  wI[k] = bfpack(0.5f * hi, 0.5f * lo);
            unpackf2(rf[k], lo, hi);  wF[k] = bfpack(0.5f * hi, 0.5f * lo);
            unpackf2(ro[k], lo, hi);  wO[k] = bfpack(0.5f * hi, 0.5f * lo);
            wG[k] = rg[k];
        }
    }
    const float bi = 0.5f * (eBih[lane]      + eBhh[lane]);
    const float bf = 0.5f * (eBih[32 + lane] + eBhh[32 + lane]);
    const float bg =        (eBih[64 + lane] + eBhh[64 + lane]);
    const float bo = 0.5f * (eBih[96 + lane] + eBhh[96 + lane]);
    const float vi = 0.5f * eWih[lane];
    const float vf = 0.5f * eWih[32 + lane];
    const float vg =        eWih[64 + lane];
    const float vo = 0.5f * eWih[96 + lane];

    ((float*)hfA[0])[lane] = 0.0f;
    ((float*)hfB[0])[lane] = 0.0f;
    hbA[0][lane] = 0;     // bf16 +0.0
    hbB[0][lane] = 0;
    __syncwarp();

    float hA = 0.0f, cA = 0.0f;
    float hB = 0.0f, cB = 0.0f;

    #pragma unroll 1
    for (int t = 0; t < SEQT; t += 2) {
        #pragma unroll
        for (int p = 0; p < 2; ++p) {
            const ulonglong2* gfA = (const ulonglong2*)hfA[p];
            const ulonglong2* gfB = (const ulonglong2*)hfB[p];
            const uint4*      bhA = (const uint4*)hbA[p];
            const uint4*      bhB = (const uint4*)hbB[p];
            const float xa = xsA[t + p];
            const float xb = xsB[t + p];

            // f32 init terms (exact; added after the dots)
            const float iniA = fmaf(xa, vi, bi), infA = fmaf(xa, vf, bf);
            const float ingA = fmaf(xa, vg, bg), inoA = fmaf(xa, vo, bo);
            const float iniB = fmaf(xb, vi, bi), infB = fmaf(xb, vf, bf);
            const float ingB = fmaf(xb, vg, bg), inoB = fmaf(xb, vo, bo);

            // ---- g gate: exact f32x2 GEMV ----
            ull agA = pack2(ingA, 0.0f);
            ull agB = pack2(ingB, 0.0f);
            #pragma unroll
            for (int k = 0; k < 8; ++k) {
                const ulonglong2 ha = gfA[k];    // LDS.128 broadcast
                const ulonglong2 hb = gfB[k];
                fma2(agA, wG[2 * k],     ha.x);
                fma2(agB, wG[2 * k],     hb.x);
                fma2(agA, wG[2 * k + 1], ha.y);
                fma2(agB, wG[2 * k + 1], hb.y);
            }

            // ---- i/f/o gates: bf16x2 HFMA2 GEMV ----
            unsigned aiA = 0, afA = 0, aoA = 0;
            unsigned aiB = 0, afB = 0, aoB = 0;
            #pragma unroll
            for (int q = 0; q < 4; ++q) {
                const uint4 ha = bhA[q];         // LDS.128: 8 bf16 h values
                const uint4 hb = bhB[q];
                hfma2(aiA, wI[4 * q + 0], ha.x);  hfma2(aiB, wI[4 * q + 0], hb.x);
                hfma2(afA, wF[4 * q + 0], ha.x);  hfma2(afB, wF[4 * q + 0], hb.x);
                hfma2(aoA, wO[4 * q + 0], ha.x);  hfma2(aoB, wO[4 * q + 0], hb.x);
                hfma2(aiA, wI[4 * q + 1], ha.y);  hfma2(aiB, wI[4 * q + 1], hb.y);
                hfma2(afA, wF[4 * q + 1], ha.y);  hfma2(afB, wF[4 * q + 1], hb.y);
                hfma2(aoA, wO[4 * q + 1], ha.y);  hfma2(aoB, wO[4 * q + 1], hb.y);
                hfma2(aiA, wI[4 * q + 2], ha.z);  hfma2(aiB, wI[4 * q + 2], hb.z);
                hfma2(afA, wF[4 * q + 2], ha.z);  hfma2(afB, wF[4 * q + 2], hb.z);
                hfma2(aoA, wO[4 * q + 2], ha.z);  hfma2(aoB, wO[4 * q + 2], hb.z);
                hfma2(aiA, wI[4 * q + 3], ha.w);  hfma2(aiB, wI[4 * q + 3], hb.w);
                hfma2(afA, wF[4 * q + 3], ha.w);  hfma2(afB, wF[4 * q + 3], hb.w);
                hfma2(aoA, wO[4 * q + 3], ha.w);  hfma2(aoB, wO[4 * q + 3], hb.w);
            }

            // ---- activations + state update (all MUFU.TANH) ----
            const float IA = sigm_pre(bfsum(aiA) + iniA);
            const float IB = sigm_pre(bfsum(aiB) + iniB);
            const float FA = sigm_pre(bfsum(afA) + infA);
            const float FB = sigm_pre(bfsum(afB) + infB);
            const float GA = tanha(hsum2(agA));
            const float GB = tanha(hsum2(agB));
            const float OA = sigm_pre(bfsum(aoA) + inoA);
            const float OB = sigm_pre(bfsum(aoB) + inoB);
            cA = fmaf(FA, cA, IA * GA);
            cB = fmaf(FB, cB, IB * GB);
            hA = OA * tanha(cA);
            hB = OB * tanha(cB);

            // publish h: f32 (for g) + bf16 (for i/f/o)
            ((float*)hfA[p ^ 1])[lane] = hA;
            ((float*)hfB[p ^ 1])[lane] = hB;
            unsigned short ha16, hb16;
            asm("cvt.rn.bf16.f32 %0, %1;" : "=h"(ha16) : "f"(hA));
            asm("cvt.rn.bf16.f32 %0, %1;" : "=h"(hb16) : "f"(hB));
            hbA[p ^ 1][lane] = ha16;
            hbB[p ^ 1][lane] = hb16;
            __syncwarp();
        }
    }

    // decoder input projection for both rows: pg = sum_j dWih[g][j]*h[j]
    float pA0 = hA * dWih[lane];
    float pA1 = hA * dWih[32 + lane];
    float pA2 = hA * dWih[64 + lane];
    float pA3 = hA * dWih[96 + lane];
    float pB0 = hB * dWih[lane];
    float pB1 = hB * dWih[32 + lane];
    float pB2 = hB * dWih[64 + lane];
    float pB3 = hB * dWih[96 + lane];
    #pragma unroll
    for (int m = 16; m > 0; m >>= 1) {
        pA0 += __shfl_xor_sync(0xffffffffu, pA0, m);
        pA1 += __shfl_xor_sync(0xffffffffu, pA1, m);
        pA2 += __shfl_xor_sync(0xffffffffu, pA2, m);
        pA3 += __shfl_xor_sync(0xffffffffu, pA3, m);
        pB0 += __shfl_xor_sync(0xffffffffu, pB0, m);
        pB1 += __shfl_xor_sync(0xffffffffu, pB1, m);
        pB2 += __shfl_xor_sync(0xffffffffu, pB2, m);
        pB3 += __shfl_xor_sync(0xffffffffu, pB3, m);
    }
    if (lane == 0) {
        g_pre[0][rA] = pA0 + dBih[0] + dBhh[0];
        g_pre[1][rA] = pA1 + dBih[1] + dBhh[1];
        g_pre[2][rA] = pA2 + dBih[2] + dBhh[2];
        g_pre[3][rA] = pA3 + dBih[3] + dBhh[3];
        g_pre[0][rB] = pB0 + dBih[0] + dBhh[0];
        g_pre[1][rB] = pB1 + dBih[1] + dBhh[1];
        g_pre[2][rB] = pB2 + dBih[2] + dBhh[2];
        g_pre[3][rB] = pB3 + dBih[3] + dBhh[3];
    }
}

// ============================================================================
// Decoder: one batch row per THREAD (H=1 scalar recurrence). 8192 threads.
// ============================================================================
__global__ void __launch_bounds__(32) dec_kernel(
    const float* __restrict__ dWhh,   // [4]
    float* __restrict__ out)          // [B, T]
{
    const int r = blockIdx.x * 32 + threadIdx.x;

    const float pre0 = 0.5f * g_pre[0][r];
    const float pre1 = 0.5f * g_pre[1][r];
    const float pre2 =        g_pre[2][r];
    const float pre3 = 0.5f * g_pre[3][r];
    const float q0 = 0.5f * dWhh[0];
    const float q1 = 0.5f * dWhh[1];
    const float q2 =        dWhh[2];
    const float q3 = 0.5f * dWhh[3];

    float hd = 0.0f, cd = 0.0f;
    float* orow = out + (size_t)r * SEQT;

    #pragma unroll 1
    for (int t = 0; t < SEQT; t += 4) {
        float v[4];
        #pragma unroll
        for (int s = 0; s < 4; ++s) {
            const float I = sigm_pre(fmaf(hd, q0, pre0));
            const float F = sigm_pre(fmaf(hd, q1, pre1));
            const float G = tanha(fmaf(hd, q2, pre2));
            const float O = sigm_pre(fmaf(hd, q3, pre3));
            cd = fmaf(F, cd, I * G);
            hd = O * tanha(cd);
            v[s] = hd;
        }
        *(float4*)(orow + t) = make_float4(v[0], v[1], v[2], v[3]);
    }
}

extern "C" void kernel_launch(void* const* d_in, const int* in_sizes, int n_in,
                              void* d_out, int out_size) {
    (void)in_sizes; (void)n_in; (void)out_size;
    enc_kernel<<<BATCH / 2, 32>>>(
        (const float*)d_in[0],
        (const float*)d_in[1], (const float*)d_in[2],
        (const float*)d_in[3], (const float*)d_in[4],
        (const float*)d_in[5],
        (const float*)d_in[7], (const float*)d_in[8]);
    dec_kernel<<<BATCH / 32, 32>>>(
        (const float*)d_in[6],
        (float*)d_out);
}

// round 12
// speedup vs baseline: 1.4835x; 1.0789x over previous
#include <cuda_runtime.h>
#include <cstdint>

typedef unsigned long long ull;

#define BATCH 8192
#define SEQT  256
#define HID   32

// scratch: decoder per-row gate preactivations, transposed for coalesced loads
__device__ float g_pre[4][BATCH];

// ---- f32x2 helpers ----
__device__ __forceinline__ void unpackf2(ull v, float &a, float &b) {
    unsigned lo, hi;
    asm("mov.b64 {%0, %1}, %2;" : "=r"(lo), "=r"(hi) : "l"(v));
    a = __uint_as_float(lo); b = __uint_as_float(hi);
}

// ---- bf16x2 helpers ----
__device__ __forceinline__ void hfma2(unsigned &acc, unsigned a, unsigned b) {
    asm("fma.rn.bf16x2 %0, %1, %2, %0;" : "+r"(acc) : "r"(a), "r"(b));
}
// pack (hi, lo) floats into bf16x2
__device__ __forceinline__ unsigned bfpack(float hi, float lo) {
    unsigned r;
    asm("cvt.rn.bf16x2.f32 %0, %1, %2;" : "=r"(r) : "f"(hi), "f"(lo));
    return r;
}
// horizontal sum of a bf16x2 accumulator in f32 (bf16->f32 is an exact shift)
__device__ __forceinline__ float bfsum(unsigned v) {
    return __uint_as_float(v << 16) + __uint_as_float(v & 0xffff0000u);
}

// ---- activations: all MUFU.TANH (error transfer measured ~1e-4 scale) ----
__device__ __forceinline__ float tanha(float x) {
    float y;
    asm("tanh.approx.f32 %0, %1;" : "=f"(y) : "f"(x));
    return y;
}
__device__ __forceinline__ float sigm_pre(float acc_half_x) {   // sig(2x) of acc
    return fmaf(0.5f, tanha(acc_half_x), 0.5f);
}

// ============================================================================
// Encoder: ONE WARP per CTA, TWO rows per warp. ALL recurrent weights in
// bf16x2 (i/f/o pre-scaled by 0.5 for the sigmoid fold; g unscaled but
// accumulated in TWO bf16x2 registers to halve rounding walk). x-term + bias
// stay exact f32, added after the dot. Single bf16 h ping-pong buffer.
// Weight regs 64/lane -> 16 warps/SM.
// ============================================================================
__global__ void __launch_bounds__(32, 16) enc_kernel(
    const float* __restrict__ x,      // [B, T]
    const float* __restrict__ eWih,   // [128]
    const float* __restrict__ eWhh,   // [128, 32]
    const float* __restrict__ eBih,   // [128]
    const float* __restrict__ eBhh,   // [128]
    const float* __restrict__ dWih,   // [4, 32]
    const float* __restrict__ dBih,   // [4]
    const float* __restrict__ dBhh)   // [4]
{
    __shared__ float xsA[SEQT], xsB[SEQT];
    __shared__ __align__(16) unsigned short hbA[2][HID], hbB[2][HID];  // bf16 h

    const int lane = threadIdx.x;
    const int rA   = blockIdx.x * 2;
    const int rB   = rA + 1;

    // stage both x rows (float4-coalesced)
    {
        const float4* a4 = (const float4*)(x + (size_t)rA * SEQT);
        const float4* b4 = (const float4*)(x + (size_t)rB * SEQT);
        ((float4*)xsA)[lane]      = a4[lane];
        ((float4*)xsA)[32 + lane] = a4[32 + lane];
        ((float4*)xsB)[lane]      = b4[lane];
        ((float4*)xsB)[32 + lane] = b4[32 + lane];
    }

    // ---- per-lane weights, all bf16x2 over k-pairs ----
    unsigned wI[16], wF[16], wG[16], wO[16];
    {
        const ull* ri = (const ull*)(eWhh + (size_t)(      lane) * HID);
        const ull* rf = (const ull*)(eWhh + (size_t)(32  + lane) * HID);
        const ull* rg = (const ull*)(eWhh + (size_t)(64  + lane) * HID);
        const ull* ro = (const ull*)(eWhh + (size_t)(96  + lane) * HID);
        #pragma unroll
        for (int k = 0; k < 16; ++k) {
            float lo, hi;
            unpackf2(ri[k], lo, hi);  wI[k] = bfpack(0.5f * hi, 0.5f * lo);
            unpackf2(rf[k], lo, hi);  wF[k] = bfpack(0.5f * hi, 0.5f * lo);
            unpackf2(rg[k], lo, hi);  wG[k] = bfpack(hi, lo);
            unpackf2(ro[k], lo, hi);  wO[k] = bfpack(0.5f * hi, 0.5f * lo);
        }
    }
    const float bi = 0.5f * (eBih[lane]      + eBhh[lane]);
    const float bf = 0.5f * (eBih[32 + lane] + eBhh[32 + lane]);
    const float bg =        (eBih[64 + lane] + eBhh[64 + lane]);
    const float bo = 0.5f * (eBih[96 + lane] + eBhh[96 + lane]);
    const float vi = 0.5f * eWih[lane];
    const float vf = 0.5f * eWih[32 + lane];
    const float vg =        eWih[64 + lane];
    const float vo = 0.5f * eWih[96 + lane];

    hbA[0][lane] = 0;     // bf16 +0.0
    hbB[0][lane] = 0;
    __syncwarp();

    float hA = 0.0f, cA = 0.0f;
    float hB = 0.0f, cB = 0.0f;

    #pragma unroll 1
    for (int t = 0; t < SEQT; t += 2) {
        #pragma unroll
        for (int p = 0; p < 2; ++p) {
            const uint4* bhA = (const uint4*)hbA[p];
            const uint4* bhB = (const uint4*)hbB[p];
            const float xa = xsA[t + p];
            const float xb = xsB[t + p];

            // f32 init terms (exact; added after the dots)
            const float iniA = fmaf(xa, vi, bi), infA = fmaf(xa, vf, bf);
            const float ingA = fmaf(xa, vg, bg), inoA = fmaf(xa, vo, bo);
            const float iniB = fmaf(xb, vi, bi), infB = fmaf(xb, vf, bf);
            const float ingB = fmaf(xb, vg, bg), inoB = fmaf(xb, vo, bo);

            // bf16x2 accumulators; g split over two to halve rounding walk
            unsigned aiA = 0, afA = 0, aoA = 0, ag0A = 0, ag1A = 0;
            unsigned aiB = 0, afB = 0, aoB = 0, ag0B = 0, ag1B = 0;

            #pragma unroll
            for (int q = 0; q < 4; ++q) {
                const uint4 ha = bhA[q];         // LDS.128: 8 bf16 h values
                const uint4 hb = bhB[q];
                hfma2(aiA,  wI[4 * q + 0], ha.x);  hfma2(aiB,  wI[4 * q + 0], hb.x);
                hfma2(afA,  wF[4 * q + 0], ha.x);  hfma2(afB,  wF[4 * q + 0], hb.x);
                hfma2(ag0A, wG[4 * q + 0], ha.x);  hfma2(ag0B, wG[4 * q + 0], hb.x);
                hfma2(aoA,  wO[4 * q + 0], ha.x);  hfma2(aoB,  wO[4 * q + 0], hb.x);
                hfma2(aiA,  wI[4 * q + 1], ha.y);  hfma2(aiB,  wI[4 * q + 1], hb.y);
                hfma2(afA,  wF[4 * q + 1], ha.y);  hfma2(afB,  wF[4 * q + 1], hb.y);
                hfma2(ag1A, wG[4 * q + 1], ha.y);  hfma2(ag1B, wG[4 * q + 1], hb.y);
                hfma2(aoA,  wO[4 * q + 1], ha.y);  hfma2(aoB,  wO[4 * q + 1], hb.y);
                hfma2(aiA,  wI[4 * q + 2], ha.z);  hfma2(aiB,  wI[4 * q + 2], hb.z);
                hfma2(afA,  wF[4 * q + 2], ha.z);  hfma2(afB,  wF[4 * q + 2], hb.z);
                hfma2(ag0A, wG[4 * q + 2], ha.z);  hfma2(ag0B, wG[4 * q + 2], hb.z);
                hfma2(aoA,  wO[4 * q + 2], ha.z);  hfma2(aoB,  wO[4 * q + 2], hb.z);
                hfma2(aiA,  wI[4 * q + 3], ha.w);  hfma2(aiB,  wI[4 * q + 3], hb.w);
                hfma2(afA,  wF[4 * q + 3], ha.w);  hfma2(afB,  wF[4 * q + 3], hb.w);
                hfma2(ag1A, wG[4 * q + 3], ha.w);  hfma2(ag1B, wG[4 * q + 3], hb.w);
                hfma2(aoA,  wO[4 * q + 3], ha.w);  hfma2(aoB,  wO[4 * q + 3], hb.w);
            }

            // ---- activations + state update (all MUFU.TANH) ----
            const float IA = sigm_pre(bfsum(aiA) + iniA);
            const float IB = sigm_pre(bfsum(aiB) + iniB);
            const float FA = sigm_pre(bfsum(afA) + infA);
            const float FB = sigm_pre(bfsum(afB) + infB);
            const float GA = tanha((bfsum(ag0A) + bfsum(ag1A)) + ingA);
            const float GB = tanha((bfsum(ag0B) + bfsum(ag1B)) + ingB);
            const float OA = sigm_pre(bfsum(aoA) + inoA);
            const float OB = sigm_pre(bfsum(aoB) + inoB);
            cA = fmaf(FA, cA, IA * GA);
            cB = fmaf(FB, cB, IB * GB);
            hA = OA * tanha(cA);
            hB = OB * tanha(cB);

            // publish h as bf16
            unsigned short ha16, hb16;
            asm("cvt.rn.bf16.f32 %0, %1;" : "=h"(ha16) : "f"(hA));
            asm("cvt.rn.bf16.f32 %0, %1;" : "=h"(hb16) : "f"(hB));
            hbA[p ^ 1][lane] = ha16;
            hbB[p ^ 1][lane] = hb16;
            __syncwarp();
        }
    }

    // decoder input projection for both rows: pg = sum_j dWih[g][j]*h[j]
    float pA0 = hA * dWih[lane];
    float pA1 = hA * dWih[32 + lane];
    float pA2 = hA * dWih[64 + lane];
    float pA3 = hA * dWih[96 + lane];
    float pB0 = hB * dWih[lane];
    float pB1 = hB * dWih[32 + lane];
    float pB2 = hB * dWih[64 + lane];
    float pB3 = hB * dWih[96 + lane];
    #pragma unroll
    for (int m = 16; m > 0; m >>= 1) {
        pA0 += __shfl_xor_sync(0xffffffffu, pA0, m);
        pA1 += __shfl_xor_sync(0xffffffffu, pA1, m);
        pA2 += __shfl_xor_sync(0xffffffffu, pA2, m);
        pA3 += __shfl_xor_sync(0xffffffffu, pA3, m);
        pB0 += __shfl_xor_sync(0xffffffffu, pB0, m);
        pB1 += __shfl_xor_sync(0xffffffffu, pB1, m);
        pB2 += __shfl_xor_sync(0xffffffffu, pB2, m);
        pB3 += __shfl_xor_sync(0xffffffffu, pB3, m);
    }
    if (lane == 0) {
        g_pre[0][rA] = pA0 + dBih[0] + dBhh[0];
        g_pre[1][rA] = pA1 + dBih[1] + dBhh[1];
        g_pre[2][rA] = pA2 + dBih[2] + dBhh[2];
        g_pre[3][rA] = pA3 + dBih[3] + dBhh[3];
        g_pre[0][rB] = pB0 + dBih[0] + dBhh[0];
        g_pre[1][rB] = pB1 + dBih[1] + dBhh[1];
        g_pre[2][rB] = pB2 + dBih[2] + dBhh[2];
        g_pre[3][rB] = pB3 + dBih[3] + dBhh[3];
    }
}

// ============================================================================
// Decoder: one batch row per THREAD (H=1 scalar recurrence). 8192 threads.
// ============================================================================
__global__ void __launch_bounds__(32) dec_kernel(
    const float* __restrict__ dWhh,   // [4]
    float* __restrict__ out)          // [B, T]
{
    const int r = blockIdx.x * 32 + threadIdx.x;

    const float pre0 = 0.5f * g_pre[0][r];
    const float pre1 = 0.5f * g_pre[1][r];
    const float pre2 =        g_pre[2][r];
    const float pre3 = 0.5f * g_pre[3][r];
    const float q0 = 0.5f * dWhh[0];
    const float q1 = 0.5f * dWhh[1];
    const float q2 =        dWhh[2];
    const float q3 = 0.5f * dWhh[3];

    float hd = 0.0f, cd = 0.0f;
    float* orow = out + (size_t)r * SEQT;

    #pragma unroll 1
    for (int t = 0; t < SEQT; t += 4) {
        float v[4];
        #pragma unroll
        for (int s = 0; s < 4; ++s) {
            const float I = sigm_pre(fmaf(hd, q0, pre0));
            const float F = sigm_pre(fmaf(hd, q1, pre1));
            const float G = tanha(fmaf(hd, q2, pre2));
            const float O = sigm_pre(fmaf(hd, q3, pre3));
            cd = fmaf(F, cd, I * G);
            hd = O * tanha(cd);
            v[s] = hd;
        }
        *(float4*)(orow + t) = make_float4(v[0], v[1], v[2], v[3]);
    }
}

extern "C" void kernel_launch(void* const* d_in, const int* in_sizes, int n_in,
                              void* d_out, int out_size) {
    (void)in_sizes; (void)n_in; (void)out_size;
    enc_kernel<<<BATCH / 2, 32>>>(
        (const float*)d_in[0],
        (const float*)d_in[1], (const float*)d_in[2],
        (const float*)d_in[3], (const float*)d_in[4],
        (const float*)d_in[5],
        (const float*)d_in[7], (const float*)d_in[8]);
    dec_kernel<<<BATCH / 32, 32>>>(
        (const float*)d_in[6],
        (float*)d_out);
}